// round 6
// baseline (speedup 1.0000x reference)
#include <cuda_runtime.h>
#include <cuda_bf16.h>
#include <cstdint>
#include <cstddef>

#define N_USERS  50000
#define N_ITEMS  10000
#define N_NODES  100000
#define EMBD     64
#define VIS_DIM  2048
#define TXT_DIM  300
#define H1V      512
#define H1T      256

#define M_PAD    10112          // 79 * 128
#define K3_VIS   (3 * 2048)     // 6144
#define KP_TXT   320            // 300 padded to 320
#define K3_TXT   (3 * KP_TXT)   // 960
#define NNZ_CAP  1700000

// ---------------- device scratch (static, no allocation) ----------------
__device__ float g_H1v[N_ITEMS * H1V];
__device__ float g_H1t[N_ITEMS * H1T];
__device__ float g_Wvd[EMBD * H1V];
__device__ float g_Wtd[EMBD * H1T];
__device__ float g_bvd[EMBD];
__device__ float g_btd[EMBD];
__device__ float g_ego[N_NODES * EMBD];
__device__ float g_cur[N_NODES * EMBD];
__device__ float g_nb [N_NODES * EMBD];
// bf16x3-split operand buffers
__device__ __nv_bfloat16 g_Av[(size_t)M_PAD * K3_VIS];
__device__ __nv_bfloat16 g_Bv[(size_t)H1V  * K3_VIS];
__device__ __nv_bfloat16 g_At[(size_t)M_PAD * K3_TXT];
__device__ __nv_bfloat16 g_Bt[(size_t)H1T  * K3_TXT];
// CSR build (packed edge: x=col, y=val bits)
__device__ int  g_deg[N_NODES];
__device__ int  g_rowstart[N_NODES + 1];
__device__ int  g_cursor[N_NODES];
__device__ long long g_pedge[NNZ_CAP];

// ================= PTX helpers (sm_80+ features only) =================
__device__ __forceinline__ uint32_t smem_u32(const void* p) {
    uint32_t a;
    asm("{ .reg .u64 t; cvta.to.shared.u64 t, %1; cvt.u32.u64 %0, t; }" : "=r"(a) : "l"(p));
    return a;
}
__device__ __forceinline__ void cp_async16(uint32_t s, const void* g) {
    asm volatile("cp.async.cg.shared.global [%0], [%1], 16;" :: "r"(s), "l"(g));
}
__device__ __forceinline__ void cp_commit() { asm volatile("cp.async.commit_group;"); }
template<int N> __device__ __forceinline__ void cp_wait() {
    asm volatile("cp.async.wait_group %0;" :: "n"(N));
}
__device__ __forceinline__ void ldm_x4(uint32_t* r, uint32_t addr) {
    asm volatile("ldmatrix.sync.aligned.m8n8.x4.shared.b16 {%0,%1,%2,%3}, [%4];"
                 : "=r"(r[0]), "=r"(r[1]), "=r"(r[2]), "=r"(r[3]) : "r"(addr));
}
__device__ __forceinline__ void mma16816(float* d, const uint32_t* a, uint32_t b0, uint32_t b1) {
    asm volatile("mma.sync.aligned.m16n8k16.row.col.f32.bf16.bf16.f32 "
                 "{%0,%1,%2,%3}, {%4,%5,%6,%7}, {%8,%9}, {%0,%1,%2,%3};"
                 : "+f"(d[0]), "+f"(d[1]), "+f"(d[2]), "+f"(d[3])
                 : "r"(a[0]), "r"(a[1]), "r"(a[2]), "r"(a[3]), "r"(b0), "r"(b1));
}
// smem tile layout: [128 rows][32 bf16] = row*64B, 4x16B chunks, XOR swizzle
__device__ __forceinline__ uint32_t toff(int r, int c) {
    return (uint32_t)((r << 6) + (((c) ^ ((r >> 1) & 3)) << 4));
}

// ---------------- fp32 -> bf16x3 split ----------------
__global__ void convert_split3(const float* __restrict__ src, __nv_bfloat16* __restrict__ dst,
                               int Msrc, int Mpad, int Ksrc, int Kpad) {
    int Kp2 = Kpad >> 1;
    int idx = blockIdx.x * blockDim.x + threadIdx.x;
    if (idx >= Mpad * Kp2) return;
    int m = idx / Kp2, kq = idx % Kp2;
    float2 v = make_float2(0.f, 0.f);
    if (m < Msrc && 2 * kq + 1 < Ksrc)
        v = *(const float2*)(src + (size_t)m * Ksrc + 2 * kq);
    __nv_bfloat16 hx = __float2bfloat16(v.x), hy = __float2bfloat16(v.y);
    __nv_bfloat162 hi; hi.x = hx; hi.y = hy;
    __nv_bfloat162 lo;
    lo.x = __float2bfloat16(v.x - __bfloat162float(hx));
    lo.y = __float2bfloat16(v.y - __bfloat162float(hy));
    __nv_bfloat162* d = (__nv_bfloat162*)dst + (size_t)m * (3 * Kp2) + kq;
    d[0] = hi;
    d[Kp2] = lo;
    d[2 * Kp2] = hi;
}
__global__ void convert_split3_b(const float* __restrict__ src, __nv_bfloat16* __restrict__ dst,
                                 int Msrc, int Ksrc, int Kpad) {
    int Kp2 = Kpad >> 1;
    int idx = blockIdx.x * blockDim.x + threadIdx.x;
    if (idx >= Msrc * Kp2) return;
    int m = idx / Kp2, kq = idx % Kp2;
    float2 v = make_float2(0.f, 0.f);
    if (2 * kq + 1 < Ksrc)
        v = *(const float2*)(src + (size_t)m * Ksrc + 2 * kq);
    __nv_bfloat16 hx = __float2bfloat16(v.x), hy = __float2bfloat16(v.y);
    __nv_bfloat162 hi; hi.x = hx; hi.y = hy;
    __nv_bfloat162 lo;
    lo.x = __float2bfloat16(v.x - __bfloat162float(hx));
    lo.y = __float2bfloat16(v.y - __bfloat162float(hy));
    __nv_bfloat162* d = (__nv_bfloat162*)dst + (size_t)m * (3 * Kp2) + kq;
    d[0] = hi;
    d[Kp2] = hi;
    d[2 * Kp2] = lo;
}

// ---------------- mma.sync bf16 GEMM: C = relu(A' @ B'^T + bias) ----------------
// BM=BN=128, BK=32, 4-stage cp.async pipeline, 256 threads, warp tile 64x32. (R3 proven)
#define GSTG 4
#define TILE_B 8192
#define STAGE_B (2 * TILE_B)
#define GSMEM (GSTG * STAGE_B)

__global__ __launch_bounds__(256)
void gemm_mma_bf16(const __nv_bfloat16* __restrict__ A, const __nv_bfloat16* __restrict__ B,
                   const float* __restrict__ bias, float* __restrict__ C,
                   int M, int Ntot, int GK, int niter) {
    extern __shared__ char smem[];
    uint32_t sbase = smem_u32(smem);
    int tid = threadIdx.x;
    int bm = blockIdx.x * 128, bn = blockIdx.y * 128;

    int r0 = tid >> 2, c0 = tid & 3;
    int r1 = r0 + 64;
    const char* gA0 = (const char*)(A + (size_t)(bm + r0) * GK) + c0 * 16;
    const char* gA1 = (const char*)(A + (size_t)(bm + r1) * GK) + c0 * 16;
    const char* gB0 = (const char*)(B + (size_t)(bn + r0) * GK) + c0 * 16;
    const char* gB1 = (const char*)(B + (size_t)(bn + r1) * GK) + c0 * 16;
    uint32_t o0 = toff(r0, c0), o1 = toff(r1, c0);

    int w = tid >> 5, lane = tid & 31;
    int wm = w & 1, wn = w >> 1;
    int lrow = lane & 15, lchk = lane >> 4;
    float acc[4][4][4];
    #pragma unroll
    for (int i = 0; i < 4; i++)
        #pragma unroll
        for (int j = 0; j < 4; j++)
            #pragma unroll
            for (int q = 0; q < 4; q++) acc[i][j][q] = 0.f;

    #pragma unroll
    for (int s = 0; s < GSTG - 1; s++) {
        if (s < niter) {
            uint32_t sb = sbase + s * STAGE_B;
            size_t go = (size_t)s * 64;
            cp_async16(sb + o0, gA0 + go);
            cp_async16(sb + o1, gA1 + go);
            cp_async16(sb + TILE_B + o0, gB0 + go);
            cp_async16(sb + TILE_B + o1, gB1 + go);
        }
        cp_commit();
    }

    for (int it = 0; it < niter; it++) {
        cp_wait<GSTG - 2>();
        __syncthreads();
        {
            int pf = it + GSTG - 1;
            if (pf < niter) {
                uint32_t sb = sbase + (pf & (GSTG - 1)) * STAGE_B;
                size_t go = (size_t)pf * 64;
                cp_async16(sb + o0, gA0 + go);
                cp_async16(sb + o1, gA1 + go);
                cp_async16(sb + TILE_B + o0, gB0 + go);
                cp_async16(sb + TILE_B + o1, gB1 + go);
            }
            cp_commit();
        }
        uint32_t sA = sbase + (it & (GSTG - 1)) * STAGE_B;
        uint32_t sB = sA + TILE_B;
        #pragma unroll
        for (int ks = 0; ks < 2; ks++) {
            uint32_t Ar[4][4], Br[2][4];
            #pragma unroll
            for (int mi = 0; mi < 4; mi++)
                ldm_x4(Ar[mi], sA + toff(wm * 64 + mi * 16 + lrow, ks * 2 + lchk));
            #pragma unroll
            for (int nj = 0; nj < 2; nj++)
                ldm_x4(Br[nj], sB + toff(wn * 32 + nj * 16 + lrow, ks * 2 + lchk));
            #pragma unroll
            for (int mi = 0; mi < 4; mi++)
                #pragma unroll
                for (int n = 0; n < 4; n++)
                    mma16816(acc[mi][n], Ar[mi], Br[n >> 1][n & 1], Br[n >> 1][2 + (n & 1)]);
        }
    }

    int g = lane >> 2, tig = lane & 3;
    #pragma unroll
    for (int mi = 0; mi < 4; mi++) {
        int gm0 = bm + wm * 64 + mi * 16 + g;
        #pragma unroll
        for (int n = 0; n < 4; n++) {
            int gn = bn + wn * 32 + n * 8 + tig * 2;
            float2 bb = *(const float2*)(bias + gn);
            if (gm0 < M) {
                float2 v;
                v.x = fmaxf(acc[mi][n][0] + bb.x, 0.f);
                v.y = fmaxf(acc[mi][n][1] + bb.y, 0.f);
                *(float2*)(C + (size_t)gm0 * Ntot + gn) = v;
            }
            if (gm0 + 8 < M) {
                float2 v;
                v.x = fmaxf(acc[mi][n][2] + bb.x, 0.f);
                v.y = fmaxf(acc[mi][n][3] + bb.y, 0.f);
                *(float2*)(C + (size_t)(gm0 + 8) * Ntot + gn) = v;
            }
        }
    }
}

// ---------------- fold Wd into Wv2 / Wt2 ----------------
__global__ void prep_weights(const float* __restrict__ Wd, const float* __restrict__ bd,
                             const float* __restrict__ Wv2, const float* __restrict__ bv2,
                             const float* __restrict__ Wt2, const float* __restrict__ bt2) {
    const int COLS = H1V + H1T + 1;
    int idx = blockIdx.x * blockDim.x + threadIdx.x;
    if (idx >= EMBD * COLS) return;
    int n = idx / COLS, c = idx % COLS;
    if (c < H1V) {
        float a = 0.f;
        #pragma unroll 8
        for (int j = 0; j < EMBD; j++) a += Wd[n * EMBD + j] * Wv2[j * H1V + c];
        g_Wvd[n * H1V + c] = a;
    } else if (c < H1V + H1T) {
        int k = c - H1V;
        float a = 0.f;
        #pragma unroll 8
        for (int j = 0; j < EMBD; j++) a += Wd[n * EMBD + j] * Wt2[j * H1T + k];
        g_Wtd[n * H1T + k] = a;
    } else {
        float av = 0.f, at = 0.f;
        for (int j = 0; j < EMBD; j++) {
            av += Wd[n * EMBD + j] * bv2[j];
            at += Wd[n * EMBD + j] * bt2[j];
        }
        g_bvd[n] = av + bd[n];
        g_btd[n] = at + bd[n];
    }
}

// ---------------- copy user/entity embeddings into ego + out[:,0:64] ----------------
__global__ void ego_init(const float4* __restrict__ emb, float* __restrict__ out) {
    int idx = blockIdx.x * blockDim.x + threadIdx.x;
    if (idx >= N_NODES * 16) return;
    int r = idx >> 4, c = idx & 15;
    if (r >= N_USERS && r < N_USERS + N_ITEMS) return;
    float4 v = emb[idx];
    ((float4*)g_ego)[idx] = v;
    *(float4*)(out + (size_t)r * 192 + c * 4) = v;
}

// ---------------- fused_item = 0.5*(H1v@Wvd^T + bvd + H1t@Wtd^T + btd) ----------------
__global__ __launch_bounds__(256)
void fuse_items(float* __restrict__ out) {
    __shared__ float As[16][68];
    __shared__ float Bs[16][68];
    int bm = blockIdx.x * 64;
    int tid = threadIdx.x;
    int tx = tid & 15, ty = tid >> 4;
    int lrow = tid >> 2, lkq = (tid & 3) << 2;
    float acc[4][4] = {};

    #pragma unroll
    for (int phase = 0; phase < 2; phase++) {
        const float* A = phase ? g_H1t : g_H1v;
        const float* W = phase ? g_Wtd : g_Wvd;
        int K = phase ? H1T : H1V;
        for (int k0 = 0; k0 < K; k0 += 16) {
            int gm = bm + lrow;
            float4 va = make_float4(0.f, 0.f, 0.f, 0.f);
            if (gm < N_ITEMS) va = *(const float4*)(A + (size_t)gm * K + k0 + lkq);
            As[lkq + 0][lrow] = va.x;
            As[lkq + 1][lrow] = va.y;
            As[lkq + 2][lrow] = va.z;
            As[lkq + 3][lrow] = va.w;
            float4 vb = *(const float4*)(W + (size_t)lrow * K + k0 + lkq);
            Bs[lkq + 0][lrow] = vb.x;
            Bs[lkq + 1][lrow] = vb.y;
            Bs[lkq + 2][lrow] = vb.z;
            Bs[lkq + 3][lrow] = vb.w;
            __syncthreads();
            #pragma unroll
            for (int kk = 0; kk < 16; kk++) {
                float4 a = *(const float4*)&As[kk][ty * 4];
                float4 b = *(const float4*)&Bs[kk][tx * 4];
                float am[4] = {a.x, a.y, a.z, a.w};
                float bn4[4] = {b.x, b.y, b.z, b.w};
                #pragma unroll
                for (int i = 0; i < 4; i++)
                    #pragma unroll
                    for (int j = 0; j < 4; j++)
                        acc[i][j] += am[i] * bn4[j];
            }
            __syncthreads();
        }
    }
    #pragma unroll
    for (int i = 0; i < 4; i++) {
        int gm = bm + ty * 4 + i;
        if (gm >= N_ITEMS) continue;
        #pragma unroll
        for (int j = 0; j < 4; j++) {
            int gn = tx * 4 + j;
            float v = 0.5f * (acc[i][j] + g_bvd[gn] + g_btd[gn]);
            g_ego[(size_t)(N_USERS + gm) * 64 + gn] = v;
            out[(size_t)(N_USERS + gm) * 192 + gn] = v;
        }
    }
}

// ================= CSR build =================
__global__ void zero_deg() {
    int i = blockIdx.x * blockDim.x + threadIdx.x;
    if (i < N_NODES) g_deg[i] = 0;
}
__global__ void hist_rows(const int* __restrict__ arow, int nnz) {
    int i = blockIdx.x * blockDim.x + threadIdx.x;
    if (i < nnz) atomicAdd(&g_deg[arow[i]], 1);
}
__global__ void scan_rows() {
    __shared__ int part[1024];
    const int CH = (N_NODES + 1023) / 1024;
    int t = threadIdx.x;
    int beg = t * CH;
    int end = beg + CH < N_NODES ? beg + CH : N_NODES;
    int s = 0;
    for (int i = beg; i < end; i++) s += g_deg[i];
    part[t] = s;
    __syncthreads();
    #pragma unroll
    for (int off = 1; off < 1024; off <<= 1) {
        int v = (t >= off) ? part[t - off] : 0;
        __syncthreads();
        part[t] += v;
        __syncthreads();
    }
    int run = (t > 0) ? part[t - 1] : 0;
    for (int i = beg; i < end; i++) {
        g_rowstart[i] = run;
        g_cursor[i] = run;
        run += g_deg[i];
    }
    if (t == 1023) g_rowstart[N_NODES] = run;
}
__global__ void scatter_edges(const int* __restrict__ arow, const int* __restrict__ acol,
                              const float* __restrict__ aval, int nnz) {
    int i = blockIdx.x * blockDim.x + threadIdx.x;
    if (i >= nnz) return;
    int r = arow[i];
    int p = atomicAdd(&g_cursor[r], 1);
    int2 e = make_int2(acol[i], __float_as_int(aval[i]));
    g_pedge[p] = *(long long*)&e;
}

// ---------------- SpMM (CSR, atomic-free, half-warp cooperative) ----------------
// 16 lanes per row. Edge batch of 16 loaded coalesced (1 edge/lane), broadcast
// within the half-warp via masked shfl; each lane gathers its float4 column.
__global__ void spmm_csr_shfl(const float4* __restrict__ cur, float4* __restrict__ nb) {
    int idx = blockIdx.x * blockDim.x + threadIdx.x;
    int row = idx >> 4;
    if (row >= N_NODES) return;
    int lane = threadIdx.x & 31;      // lane in warp
    int l16 = lane & 15;              // lane in half-warp (feature column)
    int half = lane & 16;             // 0 or 16
    unsigned mask = 0xFFFFu << half;

    int s = g_rowstart[row], e = g_rowstart[row + 1];
    float4 acc = make_float4(0.f, 0.f, 0.f, 0.f);

    for (int base = s; base < e; base += 16) {
        int n = e - base; if (n > 16) n = 16;
        long long ed = 0;
        if (base + l16 < e) ed = __ldg(&g_pedge[base + l16]);
        #pragma unroll 4
        for (int j = 0; j < n; j++) {
            long long edj = __shfl_sync(mask, ed, half + j);
            int2 cv = *(int2*)&edj;
            float v = __int_as_float(cv.y);
            float4 x = cur[(size_t)cv.x * 16 + l16];
            acc.x += v * x.x; acc.y += v * x.y; acc.z += v * x.z; acc.w += v * x.w;
        }
    }
    nb[(size_t)row * 16 + l16] = acc;
}

// ---------------- dense layer: next = leaky_relu([cur|nb] @ Wc^T + bc) ----------------
__global__ __launch_bounds__(256)
void dense_layer(const float* __restrict__ cur, const float* __restrict__ nb,
                 const float* __restrict__ Wc, const float* __restrict__ bc,
                 float* __restrict__ curout, float* __restrict__ out, int outOff) {
    __shared__ float As[16][68];
    __shared__ float Bs[16][68];
    int bm = blockIdx.x * 64;
    int tid = threadIdx.x;
    int tx = tid & 15, ty = tid >> 4;
    int lrow = tid >> 2, lkq = (tid & 3) << 2;
    float acc[4][4] = {};

    #pragma unroll
    for (int phase = 0; phase < 2; phase++) {
        const float* A = phase ? nb : cur;
        int koff = phase ? 64 : 0;
        #pragma unroll
        for (int k0 = 0; k0 < 64; k0 += 16) {
            int gm = bm + lrow;
            float4 va = (gm < N_NODES) ? *(const float4*)(A + (size_t)gm * 64 + k0 + lkq)
                                       : make_float4(0.f, 0.f, 0.f, 0.f);
            As[lkq + 0][lrow] = va.x;
            As[lkq + 1][lrow] = va.y;
            As[lkq + 2][lrow] = va.z;
            As[lkq + 3][lrow] = va.w;
            float4 vb = *(const float4*)(Wc + (size_t)lrow * 128 + koff + k0 + lkq);
            Bs[lkq + 0][lrow] = vb.x;
            Bs[lkq + 1][lrow] = vb.y;
            Bs[lkq + 2][lrow] = vb.z;
            Bs[lkq + 3][lrow] = vb.w;
            __syncthreads();
            #pragma unroll
            for (int kk = 0; kk < 16; kk++) {
                float4 a = *(const float4*)&As[kk][ty * 4];
                float4 b = *(const float4*)&Bs[kk][tx * 4];
                float am[4] = {a.x, a.y, a.z, a.w};
                float bn4[4] = {b.x, b.y, b.z, b.w};
                #pragma unroll
                for (int i = 0; i < 4; i++)
                    #pragma unroll
                    for (int j = 0; j < 4; j++)
                        acc[i][j] += am[i] * bn4[j];
            }
            __syncthreads();
        }
    }
    #pragma unroll
    for (int i = 0; i < 4; i++) {
        int gm = bm + ty * 4 + i;
        if (gm >= N_NODES) continue;
        #pragma unroll
        for (int j = 0; j < 4; j++) {
            int gn = tx * 4 + j;
            float v = acc[i][j] + bc[gn];
            v = v > 0.f ? v : 0.01f * v;
            curout[(size_t)gm * 64 + gn] = v;
            out[(size_t)gm * 192 + outOff + gn] = v;
        }
    }
}

// ---------------- launch ----------------
extern "C" void kernel_launch(void* const* d_in, const int* in_sizes, int n_in,
                              void* d_out, int out_size) {
    const int*   adj_row = (const int*)d_in[0];
    const int*   adj_col = (const int*)d_in[1];
    const float* adj_val = (const float*)d_in[2];
    const float* emb     = (const float*)d_in[3];
    const float* vf      = (const float*)d_in[4];
    const float* tf      = (const float*)d_in[5];
    const float* Wv1 = (const float*)d_in[6],  *bv1 = (const float*)d_in[7];
    const float* Wv2 = (const float*)d_in[8],  *bv2 = (const float*)d_in[9];
    const float* Wt1 = (const float*)d_in[10], *bt1 = (const float*)d_in[11];
    const float* Wt2 = (const float*)d_in[12], *bt2 = (const float*)d_in[13];
    const float* Wd  = (const float*)d_in[14], *bd  = (const float*)d_in[15];
    const float* Wc0 = (const float*)d_in[16], *bc0 = (const float*)d_in[17];
    const float* Wc1 = (const float*)d_in[18], *bc1 = (const float*)d_in[19];
    float* out = (float*)d_out;
    int nnz = in_sizes[0];
    if (nnz > NNZ_CAP) nnz = NNZ_CAP;

    float *p_h1v, *p_h1t, *p_ego, *p_cur, *p_nb;
    __nv_bfloat16 *p_Av, *p_Bv, *p_At, *p_Bt;
    cudaGetSymbolAddress((void**)&p_h1v, g_H1v);
    cudaGetSymbolAddress((void**)&p_h1t, g_H1t);
    cudaGetSymbolAddress((void**)&p_ego, g_ego);
    cudaGetSymbolAddress((void**)&p_cur, g_cur);
    cudaGetSymbolAddress((void**)&p_nb,  g_nb);
    cudaGetSymbolAddress((void**)&p_Av,  g_Av);
    cudaGetSymbolAddress((void**)&p_Bv,  g_Bv);
    cudaGetSymbolAddress((void**)&p_At,  g_At);
    cudaGetSymbolAddress((void**)&p_Bt,  g_Bt);

    cudaFuncSetAttribute(gemm_mma_bf16, cudaFuncAttributeMaxDynamicSharedMemorySize, GSMEM);

    // ---- CSR build ----
    zero_deg<<<(N_NODES + 255) / 256, 256>>>();
    hist_rows<<<(nnz + 511) / 512, 512>>>(adj_row, nnz);
    scan_rows<<<1, 1024>>>();
    scatter_edges<<<(nnz + 511) / 512, 512>>>(adj_row, adj_col, adj_val, nnz);

    // fold Wd into the second-layer MLP weights
    prep_weights<<<(EMBD * (H1V + H1T + 1) + 255) / 256, 256>>>(Wd, bd, Wv2, bv2, Wt2, bt2);

    // split fp32 operands into bf16 hi/lo triple-K layout
    convert_split3<<<((size_t)M_PAD * (2048 / 2) + 255) / 256, 256>>>(vf, p_Av, N_ITEMS, M_PAD, VIS_DIM, 2048);
    convert_split3_b<<<((size_t)H1V * (2048 / 2) + 255) / 256, 256>>>(Wv1, p_Bv, H1V, VIS_DIM, 2048);
    convert_split3<<<((size_t)M_PAD * (KP_TXT / 2) + 255) / 256, 256>>>(tf, p_At, N_ITEMS, M_PAD, TXT_DIM, KP_TXT);
    convert_split3_b<<<((size_t)H1T * (KP_TXT / 2) + 255) / 256, 256>>>(Wt1, p_Bt, H1T, TXT_DIM, KP_TXT);

    // tensor-core GEMMs (mma.sync bf16, fp32-emulated via 3-way split)
    gemm_mma_bf16<<<dim3(M_PAD / 128, H1V / 128), 256, GSMEM>>>(p_Av, p_Bv, bv1, p_h1v,
                                                                 N_ITEMS, H1V, K3_VIS, K3_VIS / 32);
    gemm_mma_bf16<<<dim3(M_PAD / 128, H1T / 128), 256, GSMEM>>>(p_At, p_Bt, bt1, p_h1t,
                                                                 N_ITEMS, H1T, K3_TXT, K3_TXT / 32);

    // ego graph
    ego_init<<<(N_NODES * 16 + 255) / 256, 256>>>((const float4*)emb, out);
    fuse_items<<<(N_ITEMS + 63) / 64, 256>>>(out);

    // layer 0: ego -> cur
    spmm_csr_shfl<<<(N_NODES * 16 + 255) / 256, 256>>>((const float4*)p_ego, (float4*)p_nb);
    dense_layer<<<(N_NODES + 63) / 64, 256>>>(p_ego, p_nb, Wc0, bc0, p_cur, out, 64);

    // layer 1: cur -> out[:,128:192]
    spmm_csr_shfl<<<(N_NODES * 16 + 255) / 256, 256>>>((const float4*)p_cur, (float4*)p_nb);
    dense_layer<<<(N_NODES + 63) / 64, 256>>>(p_cur, p_nb, Wc1, bc1, p_ego, out, 128);
}

// round 7
// speedup vs baseline: 1.1495x; 1.1495x over previous
#include <cuda_runtime.h>
#include <cuda_bf16.h>
#include <cstdint>
#include <cstddef>

#define N_USERS  50000
#define N_ITEMS  10000
#define N_NODES  100000
#define EMBD     64
#define VIS_DIM  2048
#define TXT_DIM  300
#define H1V      512
#define H1T      256

#define M_PAD    10112          // 79 * 128
#define K3_VIS   (3 * 2048)     // 6144
#define KP_TXT   320            // 300 padded to 320
#define K3_TXT   (3 * KP_TXT)   // 960

// ---------------- device scratch (static, no allocation) ----------------
__device__ float g_H1v[N_ITEMS * H1V];
__device__ float g_H1t[N_ITEMS * H1T];
__device__ float g_Wvd[EMBD * H1V];
__device__ float g_Wtd[EMBD * H1T];
__device__ float g_bvd[EMBD];
__device__ float g_btd[EMBD];
__device__ float g_ego[N_NODES * EMBD];
__device__ float g_cur[N_NODES * EMBD];
__device__ float g_nb [N_NODES * EMBD];
// bf16x3-split operand buffers
__device__ __nv_bfloat16 g_Av[(size_t)M_PAD * K3_VIS];
__device__ __nv_bfloat16 g_Bv[(size_t)H1V  * K3_VIS];
__device__ __nv_bfloat16 g_At[(size_t)M_PAD * K3_TXT];
__device__ __nv_bfloat16 g_Bt[(size_t)H1T  * K3_TXT];

// ================= PTX helpers (sm_80+ features only) =================
__device__ __forceinline__ uint32_t smem_u32(const void* p) {
    uint32_t a;
    asm("{ .reg .u64 t; cvta.to.shared.u64 t, %1; cvt.u32.u64 %0, t; }" : "=r"(a) : "l"(p));
    return a;
}
__device__ __forceinline__ void cp_async16(uint32_t s, const void* g) {
    asm volatile("cp.async.cg.shared.global [%0], [%1], 16;" :: "r"(s), "l"(g));
}
__device__ __forceinline__ void cp_commit() { asm volatile("cp.async.commit_group;"); }
template<int N> __device__ __forceinline__ void cp_wait() {
    asm volatile("cp.async.wait_group %0;" :: "n"(N));
}
__device__ __forceinline__ void ldm_x4(uint32_t* r, uint32_t addr) {
    asm volatile("ldmatrix.sync.aligned.m8n8.x4.shared.b16 {%0,%1,%2,%3}, [%4];"
                 : "=r"(r[0]), "=r"(r[1]), "=r"(r[2]), "=r"(r[3]) : "r"(addr));
}
__device__ __forceinline__ void mma16816(float* d, const uint32_t* a, uint32_t b0, uint32_t b1) {
    asm volatile("mma.sync.aligned.m16n8k16.row.col.f32.bf16.bf16.f32 "
                 "{%0,%1,%2,%3}, {%4,%5,%6,%7}, {%8,%9}, {%0,%1,%2,%3};"
                 : "+f"(d[0]), "+f"(d[1]), "+f"(d[2]), "+f"(d[3])
                 : "r"(a[0]), "r"(a[1]), "r"(a[2]), "r"(a[3]), "r"(b0), "r"(b1));
}
// smem tile layout: [128 rows][32 bf16] = row*64B, 4x16B chunks, XOR swizzle
__device__ __forceinline__ uint32_t toff(int r, int c) {
    return (uint32_t)((r << 6) + (((c) ^ ((r >> 1) & 3)) << 4));
}

// ---------------- fp32 -> bf16x3 split ----------------
__global__ void convert_split3(const float* __restrict__ src, __nv_bfloat16* __restrict__ dst,
                               int Msrc, int Mpad, int Ksrc, int Kpad) {
    int Kp2 = Kpad >> 1;
    int idx = blockIdx.x * blockDim.x + threadIdx.x;
    if (idx >= Mpad * Kp2) return;
    int m = idx / Kp2, kq = idx % Kp2;
    float2 v = make_float2(0.f, 0.f);
    if (m < Msrc && 2 * kq + 1 < Ksrc)
        v = *(const float2*)(src + (size_t)m * Ksrc + 2 * kq);
    __nv_bfloat16 hx = __float2bfloat16(v.x), hy = __float2bfloat16(v.y);
    __nv_bfloat162 hi; hi.x = hx; hi.y = hy;
    __nv_bfloat162 lo;
    lo.x = __float2bfloat16(v.x - __bfloat162float(hx));
    lo.y = __float2bfloat16(v.y - __bfloat162float(hy));
    __nv_bfloat162* d = (__nv_bfloat162*)dst + (size_t)m * (3 * Kp2) + kq;
    d[0] = hi;
    d[Kp2] = lo;
    d[2 * Kp2] = hi;
}
__global__ void convert_split3_b(const float* __restrict__ src, __nv_bfloat16* __restrict__ dst,
                                 int Msrc, int Ksrc, int Kpad) {
    int Kp2 = Kpad >> 1;
    int idx = blockIdx.x * blockDim.x + threadIdx.x;
    if (idx >= Msrc * Kp2) return;
    int m = idx / Kp2, kq = idx % Kp2;
    float2 v = make_float2(0.f, 0.f);
    if (2 * kq + 1 < Ksrc)
        v = *(const float2*)(src + (size_t)m * Ksrc + 2 * kq);
    __nv_bfloat16 hx = __float2bfloat16(v.x), hy = __float2bfloat16(v.y);
    __nv_bfloat162 hi; hi.x = hx; hi.y = hy;
    __nv_bfloat162 lo;
    lo.x = __float2bfloat16(v.x - __bfloat162float(hx));
    lo.y = __float2bfloat16(v.y - __bfloat162float(hy));
    __nv_bfloat162* d = (__nv_bfloat162*)dst + (size_t)m * (3 * Kp2) + kq;
    d[0] = hi;
    d[Kp2] = hi;
    d[2 * Kp2] = lo;
}

// ---------------- mma.sync bf16 GEMM (dual problem via blockIdx.z) ----------------
// C = relu(A' @ B'^T + bias).  BM=BN=128, BK=32, 4-stage cp.async, warp tile 64x32.
#define GSTG 4
#define TILE_B 8192
#define STAGE_B (2 * TILE_B)
#define GSMEM (GSTG * STAGE_B)

__global__ __launch_bounds__(256)
void gemm_dual(const __nv_bfloat16* __restrict__ Av, const __nv_bfloat16* __restrict__ Bv,
               const float* __restrict__ biasv, float* __restrict__ Cv,
               const __nv_bfloat16* __restrict__ At, const __nv_bfloat16* __restrict__ Bt,
               const float* __restrict__ biast, float* __restrict__ Ct) {
    // z=0: vis (N=512 -> 4 col-blocks, GK=6144); z=1: txt (N=256 -> 2 col-blocks, GK=960)
    int z = blockIdx.z;
    if (z == 1 && blockIdx.y >= H1T / 128) return;
    const __nv_bfloat16* A = z ? At : Av;
    const __nv_bfloat16* B = z ? Bt : Bv;
    const float* bias = z ? biast : biasv;
    float* C = z ? Ct : Cv;
    int Ntot = z ? H1T : H1V;
    int GK   = z ? K3_TXT : K3_VIS;
    int niter = GK / 32;
    const int M = N_ITEMS;

    extern __shared__ char smem[];
    uint32_t sbase = smem_u32(smem);
    int tid = threadIdx.x;
    int bm = blockIdx.x * 128, bn = blockIdx.y * 128;

    int r0 = tid >> 2, c0 = tid & 3;
    int r1 = r0 + 64;
    const char* gA0 = (const char*)(A + (size_t)(bm + r0) * GK) + c0 * 16;
    const char* gA1 = (const char*)(A + (size_t)(bm + r1) * GK) + c0 * 16;
    const char* gB0 = (const char*)(B + (size_t)(bn + r0) * GK) + c0 * 16;
    const char* gB1 = (const char*)(B + (size_t)(bn + r1) * GK) + c0 * 16;
    uint32_t o0 = toff(r0, c0), o1 = toff(r1, c0);

    int w = tid >> 5, lane = tid & 31;
    int wm = w & 1, wn = w >> 1;
    int lrow = lane & 15, lchk = lane >> 4;
    float acc[4][4][4];
    #pragma unroll
    for (int i = 0; i < 4; i++)
        #pragma unroll
        for (int j = 0; j < 4; j++)
            #pragma unroll
            for (int q = 0; q < 4; q++) acc[i][j][q] = 0.f;

    #pragma unroll
    for (int s = 0; s < GSTG - 1; s++) {
        if (s < niter) {
            uint32_t sb = sbase + s * STAGE_B;
            size_t go = (size_t)s * 64;
            cp_async16(sb + o0, gA0 + go);
            cp_async16(sb + o1, gA1 + go);
            cp_async16(sb + TILE_B + o0, gB0 + go);
            cp_async16(sb + TILE_B + o1, gB1 + go);
        }
        cp_commit();
    }

    for (int it = 0; it < niter; it++) {
        cp_wait<GSTG - 2>();
        __syncthreads();
        {
            int pf = it + GSTG - 1;
            if (pf < niter) {
                uint32_t sb = sbase + (pf & (GSTG - 1)) * STAGE_B;
                size_t go = (size_t)pf * 64;
                cp_async16(sb + o0, gA0 + go);
                cp_async16(sb + o1, gA1 + go);
                cp_async16(sb + TILE_B + o0, gB0 + go);
                cp_async16(sb + TILE_B + o1, gB1 + go);
            }
            cp_commit();
        }
        uint32_t sA = sbase + (it & (GSTG - 1)) * STAGE_B;
        uint32_t sB = sA + TILE_B;
        #pragma unroll
        for (int ks = 0; ks < 2; ks++) {
            uint32_t Ar[4][4], Br[2][4];
            #pragma unroll
            for (int mi = 0; mi < 4; mi++)
                ldm_x4(Ar[mi], sA + toff(wm * 64 + mi * 16 + lrow, ks * 2 + lchk));
            #pragma unroll
            for (int nj = 0; nj < 2; nj++)
                ldm_x4(Br[nj], sB + toff(wn * 32 + nj * 16 + lrow, ks * 2 + lchk));
            #pragma unroll
            for (int mi = 0; mi < 4; mi++)
                #pragma unroll
                for (int n = 0; n < 4; n++)
                    mma16816(acc[mi][n], Ar[mi], Br[n >> 1][n & 1], Br[n >> 1][2 + (n & 1)]);
        }
    }

    int g = lane >> 2, tig = lane & 3;
    #pragma unroll
    for (int mi = 0; mi < 4; mi++) {
        int gm0 = bm + wm * 64 + mi * 16 + g;
        #pragma unroll
        for (int n = 0; n < 4; n++) {
            int gn = bn + wn * 32 + n * 8 + tig * 2;
            float2 bb = *(const float2*)(bias + gn);
            if (gm0 < M) {
                float2 v;
                v.x = fmaxf(acc[mi][n][0] + bb.x, 0.f);
                v.y = fmaxf(acc[mi][n][1] + bb.y, 0.f);
                *(float2*)(C + (size_t)gm0 * Ntot + gn) = v;
            }
            if (gm0 + 8 < M) {
                float2 v;
                v.x = fmaxf(acc[mi][n][2] + bb.x, 0.f);
                v.y = fmaxf(acc[mi][n][3] + bb.y, 0.f);
                *(float2*)(C + (size_t)(gm0 + 8) * Ntot + gn) = v;
            }
        }
    }
}

// ---------------- fold Wd into Wv2 / Wt2 ----------------
__global__ void prep_weights(const float* __restrict__ Wd, const float* __restrict__ bd,
                             const float* __restrict__ Wv2, const float* __restrict__ bv2,
                             const float* __restrict__ Wt2, const float* __restrict__ bt2) {
    const int COLS = H1V + H1T + 1;
    int idx = blockIdx.x * blockDim.x + threadIdx.x;
    if (idx >= EMBD * COLS) return;
    int n = idx / COLS, c = idx % COLS;
    if (c < H1V) {
        float a = 0.f;
        #pragma unroll 8
        for (int j = 0; j < EMBD; j++) a += Wd[n * EMBD + j] * Wv2[j * H1V + c];
        g_Wvd[n * H1V + c] = a;
    } else if (c < H1V + H1T) {
        int k = c - H1V;
        float a = 0.f;
        #pragma unroll 8
        for (int j = 0; j < EMBD; j++) a += Wd[n * EMBD + j] * Wt2[j * H1T + k];
        g_Wtd[n * H1T + k] = a;
    } else {
        float av = 0.f, at = 0.f;
        for (int j = 0; j < EMBD; j++) {
            av += Wd[n * EMBD + j] * bv2[j];
            at += Wd[n * EMBD + j] * bt2[j];
        }
        g_bvd[n] = av + bd[n];
        g_btd[n] = at + bd[n];
    }
}

// ---------------- copy user/entity embeddings into ego + out[:,0:64] ----------------
__global__ void ego_init(const float4* __restrict__ emb, float* __restrict__ out) {
    int idx = blockIdx.x * blockDim.x + threadIdx.x;
    if (idx >= N_NODES * 16) return;
    int r = idx >> 4, c = idx & 15;
    if (r >= N_USERS && r < N_USERS + N_ITEMS) return;
    float4 v = emb[idx];
    ((float4*)g_ego)[idx] = v;
    *(float4*)(out + (size_t)r * 192 + c * 4) = v;
}

// ---------------- fused_item = 0.5*(H1v@Wvd^T + bvd + H1t@Wtd^T + btd) ----------------
__global__ __launch_bounds__(256)
void fuse_items(float* __restrict__ out) {
    __shared__ float As[16][68];
    __shared__ float Bs[16][68];
    int bm = blockIdx.x * 64;
    int tid = threadIdx.x;
    int tx = tid & 15, ty = tid >> 4;
    int lrow = tid >> 2, lkq = (tid & 3) << 2;
    float acc[4][4] = {};

    #pragma unroll
    for (int phase = 0; phase < 2; phase++) {
        const float* A = phase ? g_H1t : g_H1v;
        const float* W = phase ? g_Wtd : g_Wvd;
        int K = phase ? H1T : H1V;
        for (int k0 = 0; k0 < K; k0 += 16) {
            int gm = bm + lrow;
            float4 va = make_float4(0.f, 0.f, 0.f, 0.f);
            if (gm < N_ITEMS) va = *(const float4*)(A + (size_t)gm * K + k0 + lkq);
            As[lkq + 0][lrow] = va.x;
            As[lkq + 1][lrow] = va.y;
            As[lkq + 2][lrow] = va.z;
            As[lkq + 3][lrow] = va.w;
            float4 vb = *(const float4*)(W + (size_t)lrow * K + k0 + lkq);
            Bs[lkq + 0][lrow] = vb.x;
            Bs[lkq + 1][lrow] = vb.y;
            Bs[lkq + 2][lrow] = vb.z;
            Bs[lkq + 3][lrow] = vb.w;
            __syncthreads();
            #pragma unroll
            for (int kk = 0; kk < 16; kk++) {
                float4 a = *(const float4*)&As[kk][ty * 4];
                float4 b = *(const float4*)&Bs[kk][tx * 4];
                float am[4] = {a.x, a.y, a.z, a.w};
                float bn4[4] = {b.x, b.y, b.z, b.w};
                #pragma unroll
                for (int i = 0; i < 4; i++)
                    #pragma unroll
                    for (int j = 0; j < 4; j++)
                        acc[i][j] += am[i] * bn4[j];
            }
            __syncthreads();
        }
    }
    #pragma unroll
    for (int i = 0; i < 4; i++) {
        int gm = bm + ty * 4 + i;
        if (gm >= N_ITEMS) continue;
        #pragma unroll
        for (int j = 0; j < 4; j++) {
            int gn = tx * 4 + j;
            float v = 0.5f * (acc[i][j] + g_bvd[gn] + g_btd[gn]);
            g_ego[(size_t)(N_USERS + gm) * 64 + gn] = v;
            out[(size_t)(N_USERS + gm) * 192 + gn] = v;
        }
    }
}

// ---------------- zero the SpMM accumulator ----------------
__global__ void zero_nb() {
    int idx = blockIdx.x * blockDim.x + threadIdx.x;
    if (idx < N_NODES * 16) ((float4*)g_nb)[idx] = make_float4(0.f, 0.f, 0.f, 0.f);
}

// ---------------- SpMM: nb[row] += val * cur[col], float4 atomics (R3 proven) ----------------
__global__ void spmm_atomic(const int* __restrict__ arow, const int* __restrict__ acol,
                            const float* __restrict__ aval, const float4* __restrict__ cur,
                            float4* __restrict__ nb, int nnz) {
    int idx = blockIdx.x * blockDim.x + threadIdx.x;
    int e = idx >> 4, l = idx & 15;
    if (e >= nnz) return;
    int r = arow[e];
    int c = acol[e];
    float v = aval[e];
    float4 x = cur[(size_t)c * 16 + l];
    float4 m = make_float4(v * x.x, v * x.y, v * x.z, v * x.w);
#if __CUDA_ARCH__ >= 900
    atomicAdd(nb + (size_t)r * 16 + l, m);
#else
    float* p = (float*)(nb + (size_t)r * 16 + l);
    atomicAdd(p + 0, m.x);
    atomicAdd(p + 1, m.y);
    atomicAdd(p + 2, m.z);
    atomicAdd(p + 3, m.w);
#endif
}

// ---------------- dense layer: next = leaky_relu([cur|nb] @ Wc^T + bc) ----------------
__global__ __launch_bounds__(256)
void dense_layer(const float* __restrict__ cur, const float* __restrict__ nb,
                 const float* __restrict__ Wc, const float* __restrict__ bc,
                 float* __restrict__ curout, float* __restrict__ out, int outOff) {
    __shared__ float As[16][68];
    __shared__ float Bs[16][68];
    int bm = blockIdx.x * 64;
    int tid = threadIdx.x;
    int tx = tid & 15, ty = tid >> 4;
    int lrow = tid >> 2, lkq = (tid & 3) << 2;
    float acc[4][4] = {};

    #pragma unroll
    for (int phase = 0; phase < 2; phase++) {
        const float* A = phase ? nb : cur;
        int koff = phase ? 64 : 0;
        #pragma unroll
        for (int k0 = 0; k0 < 64; k0 += 16) {
            int gm = bm + lrow;
            float4 va = (gm < N_NODES) ? *(const float4*)(A + (size_t)gm * 64 + k0 + lkq)
                                       : make_float4(0.f, 0.f, 0.f, 0.f);
            As[lkq + 0][lrow] = va.x;
            As[lkq + 1][lrow] = va.y;
            As[lkq + 2][lrow] = va.z;
            As[lkq + 3][lrow] = va.w;
            float4 vb = *(const float4*)(Wc + (size_t)lrow * 128 + koff + k0 + lkq);
            Bs[lkq + 0][lrow] = vb.x;
            Bs[lkq + 1][lrow] = vb.y;
            Bs[lkq + 2][lrow] = vb.z;
            Bs[lkq + 3][lrow] = vb.w;
            __syncthreads();
            #pragma unroll
            for (int kk = 0; kk < 16; kk++) {
                float4 a = *(const float4*)&As[kk][ty * 4];
                float4 b = *(const float4*)&Bs[kk][tx * 4];
                float am[4] = {a.x, a.y, a.z, a.w};
                float bn4[4] = {b.x, b.y, b.z, b.w};
                #pragma unroll
                for (int i = 0; i < 4; i++)
                    #pragma unroll
                    for (int j = 0; j < 4; j++)
                        acc[i][j] += am[i] * bn4[j];
            }
            __syncthreads();
        }
    }
    #pragma unroll
    for (int i = 0; i < 4; i++) {
        int gm = bm + ty * 4 + i;
        if (gm >= N_NODES) continue;
        #pragma unroll
        for (int j = 0; j < 4; j++) {
            int gn = tx * 4 + j;
            float v = acc[i][j] + bc[gn];
            v = v > 0.f ? v : 0.01f * v;
            curout[(size_t)gm * 64 + gn] = v;
            out[(size_t)gm * 192 + outOff + gn] = v;
        }
    }
}

// ---------------- launch ----------------
extern "C" void kernel_launch(void* const* d_in, const int* in_sizes, int n_in,
                              void* d_out, int out_size) {
    const int*   adj_row = (const int*)d_in[0];
    const int*   adj_col = (const int*)d_in[1];
    const float* adj_val = (const float*)d_in[2];
    const float* emb     = (const float*)d_in[3];
    const float* vf      = (const float*)d_in[4];
    const float* tf      = (const float*)d_in[5];
    const float* Wv1 = (const float*)d_in[6],  *bv1 = (const float*)d_in[7];
    const float* Wv2 = (const float*)d_in[8],  *bv2 = (const float*)d_in[9];
    const float* Wt1 = (const float*)d_in[10], *bt1 = (const float*)d_in[11];
    const float* Wt2 = (const float*)d_in[12], *bt2 = (const float*)d_in[13];
    const float* Wd  = (const float*)d_in[14], *bd  = (const float*)d_in[15];
    const float* Wc0 = (const float*)d_in[16], *bc0 = (const float*)d_in[17];
    const float* Wc1 = (const float*)d_in[18], *bc1 = (const float*)d_in[19];
    float* out = (float*)d_out;
    int nnz = in_sizes[0];

    float *p_h1v, *p_h1t, *p_ego, *p_cur, *p_nb;
    __nv_bfloat16 *p_Av, *p_Bv, *p_At, *p_Bt;
    cudaGetSymbolAddress((void**)&p_h1v, g_H1v);
    cudaGetSymbolAddress((void**)&p_h1t, g_H1t);
    cudaGetSymbolAddress((void**)&p_ego, g_ego);
    cudaGetSymbolAddress((void**)&p_cur, g_cur);
    cudaGetSymbolAddress((void**)&p_nb,  g_nb);
    cudaGetSymbolAddress((void**)&p_Av,  g_Av);
    cudaGetSymbolAddress((void**)&p_Bv,  g_Bv);
    cudaGetSymbolAddress((void**)&p_At,  g_At);
    cudaGetSymbolAddress((void**)&p_Bt,  g_Bt);

    cudaFuncSetAttribute(gemm_dual, cudaFuncAttributeMaxDynamicSharedMemorySize, GSMEM);

    // 1-5: weight fold + operand splits (launch order keeps gemm_dual at slot 6 for ncu -s 5)
    prep_weights<<<(EMBD * (H1V + H1T + 1) + 255) / 256, 256>>>(Wd, bd, Wv2, bv2, Wt2, bt2);
    convert_split3<<<((size_t)M_PAD * (2048 / 2) + 255) / 256, 256>>>(vf, p_Av, N_ITEMS, M_PAD, VIS_DIM, 2048);
    convert_split3_b<<<((size_t)H1V * (2048 / 2) + 255) / 256, 256>>>(Wv1, p_Bv, H1V, VIS_DIM, 2048);
    convert_split3<<<((size_t)M_PAD * (KP_TXT / 2) + 255) / 256, 256>>>(tf, p_At, N_ITEMS, M_PAD, TXT_DIM, KP_TXT);
    convert_split3_b<<<((size_t)H1T * (KP_TXT / 2) + 255) / 256, 256>>>(Wt1, p_Bt, H1T, TXT_DIM, KP_TXT);

    // 6: both item-MLP layer-1 GEMMs in one launch (z=0 vis, z=1 txt)
    gemm_dual<<<dim3(M_PAD / 128, H1V / 128, 2), 256, GSMEM>>>(p_Av, p_Bv, bv1, p_h1v,
                                                               p_At, p_Bt, bt1, p_h1t);

    // ego graph
    ego_init<<<(N_NODES * 16 + 255) / 256, 256>>>((const float4*)emb, out);
    fuse_items<<<(N_ITEMS + 63) / 64, 256>>>(out);

    int spmm_blocks = (nnz * 16 + 255) / 256;

    // layer 0: ego -> cur
    zero_nb<<<(N_NODES * 16 + 255) / 256, 256>>>();
    spmm_atomic<<<spmm_blocks, 256>>>(adj_row, adj_col, adj_val,
                                      (const float4*)p_ego, (float4*)p_nb, nnz);
    dense_layer<<<(N_NODES + 63) / 64, 256>>>(p_ego, p_nb, Wc0, bc0, p_cur, out, 64);

    // layer 1: cur -> out[:,128:192]
    zero_nb<<<(N_NODES * 16 + 255) / 256, 256>>>();
    spmm_atomic<<<spmm_blocks, 256>>>(adj_row, adj_col, adj_val,
                                      (const float4*)p_cur, (float4*)p_nb, nnz);
    dense_layer<<<(N_NODES + 63) / 64, 256>>>(p_cur, p_nb, Wc1, bc1, p_ego, out, 128);
}